// round 11
// baseline (speedup 1.0000x reference)
#include <cuda_runtime.h>
#include <math.h>

// Problem constants
#define BTT     16
#define NM      1024
#define NL      64
#define NKV     1088
#define DIMM    128
#define HEADS   8
#define INNER   2048
#define QSCALE  0.08838834764831845f   // 128^-0.5
#define KVHALF  544

// Static device scratch
static __device__ float  g_pp[2 * 4 * 8 * DIMM * DIMM];       // split-K prep partials
static __device__ float  g_m [HEADS * DIMM * DIMM];           // M_h = scale*Wq_h@Wk_h^T
static __device__ float  g_n [HEADS * DIMM * DIMM];           // N_h = Wv_h@Wo_h
static __device__ float  g_po[2 * BTT * HEADS * NL * DIMM];   // un-normalized O halves
static __device__ float2 g_ml2[2 * BTT * HEADS * NL];         // (m, l) per half per row
static __device__ float  g_fp [BTT * HEADS * NL * DIMM];      // per-head partials of out

// fp32 -> tf32 round-to-nearest
__device__ __forceinline__ float cf(float x){
    unsigned u; asm("cvt.rna.tf32.f32 %0, %1;" : "=r"(u) : "f"(x));
    return __uint_as_float(u);
}

__device__ __forceinline__ void mma8(float* d, const unsigned* a, const unsigned* b){
    asm volatile("mma.sync.aligned.m16n8k8.row.col.f32.tf32.tf32.f32 "
        "{%0,%1,%2,%3}, {%4,%5,%6,%7}, {%8,%9}, {%0,%1,%2,%3};"
        : "+f"(d[0]), "+f"(d[1]), "+f"(d[2]), "+f"(d[3])
        : "r"(a[0]), "r"(a[1]), "r"(a[2]), "r"(a[3]), "r"(b[0]), "r"(b[1]));
}

// row r of concat(tensor[bt], latents[bt])
__device__ __forceinline__ const float* row_ptr(
    const float* __restrict__ tensor, const float* __restrict__ latents, int bt, int r)
{
    return (r < NM) ? tensor  + ((size_t)bt * NM + r)        * DIMM
                    : latents + ((size_t)bt * NL + (r - NM)) * DIMM;
}

// ===========================================================================
// Flash building blocks: 256 threads (8 warps).
// ===========================================================================
#define BSW 4352   // words per gemm_w staging buffer (32*136)

// full-width fragment compute (QW phase): warp tile 16x64, B in Bs[32][136]
__device__ __forceinline__ void frag_compute(
    const float* __restrict__ At, const float* __restrict__ Bs,
    float acc[8][4], int wm, int wn, int grp, int qid, int kbase)
{
    #pragma unroll
    for (int kk = 0; kk < 32; kk += 8) {
        unsigned a[4], b[8][2];
        const int k0 = kbase + kk;
        a[0] = __float_as_uint(At[(k0+qid  )*72 + wm+grp  ]);
        a[1] = __float_as_uint(At[(k0+qid  )*72 + wm+grp+8]);
        a[2] = __float_as_uint(At[(k0+qid+4)*72 + wm+grp  ]);
        a[3] = __float_as_uint(At[(k0+qid+4)*72 + wm+grp+8]);
        #pragma unroll
        for (int j = 0; j < 8; j++) {
            b[j][0] = __float_as_uint(Bs[(kk+qid  )*136 + wn+8*j+grp]);
            b[j][1] = __float_as_uint(Bs[(kk+qid+4)*136 + wn+8*j+grp]);
        }
        #pragma unroll
        for (int j = 0; j < 8; j++) mma8(acc[j], a, b[j]);
    }
}

__device__ __forceinline__ void stage_nn(float* Bs, const float4* pre, int br, int bc){
    #pragma unroll
    for (int i = 0; i < 4; i++) {
        float4 v;
        v.x = cf(pre[i].x); v.y = cf(pre[i].y);
        v.z = cf(pre[i].z); v.w = cf(pre[i].w);
        *(float4*)&Bs[br*136 + bc + 4*i] = v;
    }
}

// NN with contiguous weight B[k][n] (ldb row stride), K multiple of 32 (QW phase)
__device__ __forceinline__ void gemm_w(
    const float* __restrict__ At, const float* __restrict__ Bg, int ldb, int K,
    float acc[8][4], float* __restrict__ BsBase,
    int wm, int wn, int grp, int qid, int t)
{
    const int br = t >> 3, bc = (t & 7) * 16;
    const float* Bp = Bg + (size_t)br * ldb + bc;
    float4 pre[4];
    #pragma unroll
    for (int i = 0; i < 4; i++) pre[i] = *(const float4*)(Bp + 4*i);
    stage_nn(BsBase, pre, br, bc);
    const int nk = K / 32;
    for (int c = 0; c < nk; c++) {
        __syncthreads();
        if (c + 1 < nk) {
            const float* Bp2 = Bp + (size_t)(c + 1) * 32 * ldb;
            #pragma unroll
            for (int i = 0; i < 4; i++) pre[i] = *(const float4*)(Bp2 + 4*i);
        }
        frag_compute(At, BsBase + (c & 1) * BSW, acc, wm, wn, grp, qid, c * 32);
        if (c + 1 < nk) stage_nn(BsBase + ((c + 1) & 1) * BSW, pre, br, bc);
    }
}

// S-phase fragments: A = QWt[k][72] (K=128 dims), B = inS read transposed
// (b at [n*136 + k]; 2-way bank conflict, no staging). sacc warp tile 16x32.
__device__ __forceinline__ void frag_s(
    const float* __restrict__ QWt, const float* __restrict__ inS,
    float sacc[4][4], int wm, int wn2, int grp, int qid)
{
    #pragma unroll
    for (int kk = 0; kk < DIMM; kk += 8) {
        unsigned a[4], b[4][2];
        a[0] = __float_as_uint(QWt[(kk+qid  )*72 + wm+grp  ]);
        a[1] = __float_as_uint(QWt[(kk+qid  )*72 + wm+grp+8]);
        a[2] = __float_as_uint(QWt[(kk+qid+4)*72 + wm+grp  ]);
        a[3] = __float_as_uint(QWt[(kk+qid+4)*72 + wm+grp+8]);
        #pragma unroll
        for (int j = 0; j < 4; j++) {
            const float* rp = inS + (size_t)(wn2 + 8*j + grp) * 136 + kk + qid;
            b[j][0] = __float_as_uint(rp[0]);
            b[j][1] = __float_as_uint(rp[4]);
        }
        #pragma unroll
        for (int j = 0; j < 4; j++) mma8(sacc[j], a, b[j]);
    }
}

// PV-phase fragments: A = SXt (P, [kv][72]), B = inS natural ([k*136+n],
// conflict-free). K = valid kv (multiple of 8). Warp tile 16x64 over dims.
__device__ __forceinline__ void frag_pv(
    const float* __restrict__ SXt, const float* __restrict__ inS,
    float O[8][4], int wm, int wn, int grp, int qid, int K)
{
    #pragma unroll 4
    for (int kk = 0; kk < K; kk += 8) {
        unsigned a[4], b[8][2];
        a[0] = __float_as_uint(SXt[(kk+qid  )*72 + wm+grp  ]);
        a[1] = __float_as_uint(SXt[(kk+qid  )*72 + wm+grp+8]);
        a[2] = __float_as_uint(SXt[(kk+qid+4)*72 + wm+grp  ]);
        a[3] = __float_as_uint(SXt[(kk+qid+4)*72 + wm+grp+8]);
        #pragma unroll
        for (int j = 0; j < 8; j++) {
            b[j][0] = __float_as_uint(inS[(kk+qid  )*136 + wn+8*j+grp]);
            b[j][1] = __float_as_uint(inS[(kk+qid+4)*136 + wn+8*j+grp]);
        }
        #pragma unroll
        for (int j = 0; j < 8; j++) mma8(O[j], a, b[j]);
    }
}

// ===========================================================================
// k_flash: grid 256 = (bt,h,half). KV blocks of 64 rows staged ONCE into
// resident inS[64][136]; S reads it transposed, PV reads it natural.
// smem words: QWt 9216 | SXt 9216 | inS 8704 | stats 192 = 109312 bytes.
// ===========================================================================
#define FLASH_WORDS (9216 + 9216 + 2*BSW + 192)
#define FLASH_SMEM  (FLASH_WORDS * 4)

__global__ void __launch_bounds__(256, 2) k_flash(
    const float* __restrict__ tensor, const float* __restrict__ latents)
{
    extern __shared__ float sm[];
    float* QWt   = sm;                    // [128 dims][72 rows]
    float* SXt   = sm + 9216;             // latents staging, then S/P [64 kv][72]
    float* inS   = sm + 2*9216;           // [64 kv][136] resident tile (QW: 2x[32][136])
    float* m_run = inS + 2*BSW;           // [64]
    float* l_run = m_run + 64;
    float* rsc   = l_run + 64;

    const int zz = blockIdx.x;
    const int z = zz >> 1, half = zz & 1;
    const int bt = z >> 3, h = z & 7;
    const int kvbase = half * KVHALF;

    const int t = threadIdx.x, warp = t >> 5, lane = t & 31;
    const int grp = lane >> 2, qid = lane & 3;
    const int wm = (warp & 3) * 16;
    const int wn = (warp >> 2) * 64;      // full-width N offset (dims)
    const int wn2 = (warp >> 2) * 32;     // half-width N offset (kv)

    if (t < 64) { m_run[t] = -INFINITY; l_run[t] = 0.f; }

    // stage latents[bt] (64x128) transposed -> SXt[k][r]
    {
        const int r = t >> 2, k0 = (t & 3) * 32;
        const float* Lp = latents + (size_t)bt * NL * DIMM + (size_t)r * DIMM + k0;
        #pragma unroll
        for (int i = 0; i < 8; i++) {
            float4 v = *(const float4*)(Lp + 4*i);
            const int k = k0 + 4*i;
            SXt[(k+0)*72 + r] = cf(v.x);
            SXt[(k+1)*72 + r] = cf(v.y);
            SXt[(k+2)*72 + r] = cf(v.z);
            SXt[(k+3)*72 + r] = cf(v.w);
        }
    }
    __syncthreads();

    // QW = lat @ M_h (double-buffered staging in the inS region)
    {
        float qacc[8][4];
        #pragma unroll
        for (int j = 0; j < 8; j++)
            #pragma unroll
            for (int i = 0; i < 4; i++) qacc[j][i] = 0.f;
        gemm_w(SXt, g_m + (size_t)h * DIMM * DIMM, DIMM, DIMM,
               qacc, inS, wm, wn, grp, qid, t);
        #pragma unroll
        for (int j = 0; j < 8; j++) {
            const int c = wn + 8*j + 2*qid;
            QWt[(c  )*72 + wm+grp  ] = cf(qacc[j][0]);
            QWt[(c+1)*72 + wm+grp  ] = cf(qacc[j][1]);
            QWt[(c  )*72 + wm+grp+8] = cf(qacc[j][2]);
            QWt[(c+1)*72 + wm+grp+8] = cf(qacc[j][3]);
        }
    }
    __syncthreads();   // QWt visible; SXt latents reads done; inS free

    float O[8][4];
    #pragma unroll
    for (int j = 0; j < 8; j++)
        #pragma unroll
        for (int i = 0; i < 4; i++) O[j][i] = 0.f;

    for (int kv0 = 0; kv0 < KVHALF; kv0 += 64) {
        const int valid = (KVHALF - kv0 < 64) ? (KVHALF - kv0) : 64;   // 64 or 32

        // ---- stage in rows [kv0, kv0+64) once: inS[row][dim] (tf32) ----
        {
            const int srow = t >> 2, sc0 = (t & 3) * 32;
            float* dst = inS + (size_t)srow * 136 + sc0;
            if (srow < valid) {
                const float* Bp = row_ptr(tensor, latents, bt, kvbase + kv0 + srow) + sc0;
                #pragma unroll
                for (int i = 0; i < 8; i++) {
                    float4 v = *(const float4*)(Bp + 4*i);
                    float4 w;
                    w.x = cf(v.x); w.y = cf(v.y); w.z = cf(v.z); w.w = cf(v.w);
                    *(float4*)(dst + 4*i) = w;
                }
            } else {
                const float4 zz4 = make_float4(0.f,0.f,0.f,0.f);
                #pragma unroll
                for (int i = 0; i < 8; i++) *(float4*)(dst + 4*i) = zz4;
            }
        }
        __syncthreads();

        // ---- S = QW @ in^T (no staging, no inner syncs) ----
        {
            float sacc[4][4];
            #pragma unroll
            for (int j = 0; j < 4; j++)
                #pragma unroll
                for (int i = 0; i < 4; i++) sacc[j][i] = 0.f;
            frag_s(QWt, inS, sacc, wm, wn2, grp, qid);
            #pragma unroll
            for (int j = 0; j < 4; j++) {
                const int c = wn2 + 8*j + 2*qid;
                SXt[(c  )*72 + wm+grp  ] = sacc[j][0];
                SXt[(c  )*72 + wm+grp+8] = sacc[j][2];
                SXt[(c+1)*72 + wm+grp  ] = sacc[j][1];
                SXt[(c+1)*72 + wm+grp+8] = sacc[j][3];
            }
        }
        __syncthreads();

        // ---- online softmax: 4 threads per row, 16 cols each ----
        {
            const int row = t >> 2, part = t & 3;
            const float mo = m_run[row];
            float mx = mo;
            #pragma unroll 8
            for (int i = 0; i < 16; i++) {
                const int c = part + 4*i;
                if (c < valid) mx = fmaxf(mx, SXt[c*72 + row]);
            }
            mx = fmaxf(mx, __shfl_xor_sync(0xffffffffu, mx, 1));
            mx = fmaxf(mx, __shfl_xor_sync(0xffffffffu, mx, 2));
            float s = 0.f;
            #pragma unroll 8
            for (int i = 0; i < 16; i++) {
                const int c = part + 4*i;
                if (c < valid) {
                    const float e = __expf(SXt[c*72 + row] - mx);
                    SXt[c*72 + row] = cf(e);
                    s += e;
                }
            }
            s += __shfl_xor_sync(0xffffffffu, s, 1);
            s += __shfl_xor_sync(0xffffffffu, s, 2);
            if (part == 0) {
                const float scale = __expf(mo - mx);
                l_run[row] = l_run[row] * scale + s;
                m_run[row] = mx;
                rsc[row]   = scale;
            }
        }
        __syncthreads();

        // ---- rescale O, then O += P @ in_blk (resident operands) ----
        {
            const float s0 = rsc[wm+grp], s1 = rsc[wm+grp+8];
            #pragma unroll
            for (int j = 0; j < 8; j++) {
                O[j][0] *= s0; O[j][1] *= s0;
                O[j][2] *= s1; O[j][3] *= s1;
            }
        }
        frag_pv(SXt, inS, O, wm, wn, grp, qid, valid);
        __syncthreads();   // all inS/SXt reads done before next block restages
    }

    if (t < 64) g_ml2[(size_t)zz * NL + t] = make_float2(m_run[t], l_run[t]);
    float* P = g_po + (size_t)zz * NL * DIMM;
    #pragma unroll
    for (int j = 0; j < 8; j++) {
        const int c = wn + 8*j + 2*qid;
        *(float2*)&P[(size_t)(wm+grp  ) * DIMM + c] = make_float2(O[j][0], O[j][1]);
        *(float2*)&P[(size_t)(wm+grp+8) * DIMM + c] = make_float2(O[j][2], O[j][3]);
    }
}

// ===========================================================================
// fp32 64x64 cores for split-K weight precompute (proven)
// ===========================================================================
__device__ __forceinline__ void f32_nn_core(
    const float* __restrict__ A, const float* __restrict__ B, float* __restrict__ C,
    int lda, int ldb, int ldc, int K, float alpha, int m0, int n0)
{
    __shared__ float As[16][68];
    __shared__ float Bsb[16][68];
    const int t  = threadIdx.x;
    const int tx = t & 15, ty = t >> 4;
    const int am = t >> 2, ak = (t & 3) << 2;
    const int bk = t >> 4, bn = (t & 15) << 2;
    const float* Ap = A + (size_t)(m0 + am) * lda + ak;
    const float* Bp = B + (size_t)bk * ldb + n0 + bn;
    float acc[4][4] = {};
    for (int kb = 0; kb < K; kb += 16) {
        float4 a = *(const float4*)(Ap + kb);
        float4 b = *(const float4*)(Bp + (size_t)kb * ldb);
        As[ak+0][am] = a.x; As[ak+1][am] = a.y; As[ak+2][am] = a.z; As[ak+3][am] = a.w;
        *(float4*)&Bsb[bk][bn] = b;
        __syncthreads();
        #pragma unroll
        for (int k = 0; k < 16; ++k) {
            float4 av = *(const float4*)&As[k][ty << 2];
            float4 bv = *(const float4*)&Bsb[k][tx << 2];
            acc[0][0] += av.x*bv.x; acc[0][1] += av.x*bv.y; acc[0][2] += av.x*bv.z; acc[0][3] += av.x*bv.w;
            acc[1][0] += av.y*bv.x; acc[1][1] += av.y*bv.y; acc[1][2] += av.y*bv.z; acc[1][3] += av.y*bv.w;
            acc[2][0] += av.z*bv.x; acc[2][1] += av.z*bv.y; acc[2][2] += av.z*bv.z; acc[2][3] += av.z*bv.w;
            acc[3][0] += av.w*bv.x; acc[3][1] += av.w*bv.y; acc[3][2] += av.w*bv.z; acc[3][3] += av.w*bv.w;
        }
        __syncthreads();
    }
    #pragma unroll
    for (int i = 0; i < 4; ++i) {
        float4 r;
        r.x = acc[i][0]*alpha; r.y = acc[i][1]*alpha; r.z = acc[i][2]*alpha; r.w = acc[i][3]*alpha;
        *(float4*)&C[(size_t)(m0 + (ty << 2) + i) * ldc + n0 + (tx << 2)] = r;
    }
}

__device__ __forceinline__ void f32_nt_core(
    const float* __restrict__ A, const float* __restrict__ Bm, float* __restrict__ C,
    int lda, int ldb, int ldc, int K, float alpha, int m0, int n0)
{
    __shared__ float As[16][68];
    __shared__ float Bsb[16][68];
    const int t  = threadIdx.x;
    const int tx = t & 15, ty = t >> 4;
    const int am = t >> 2, ak = (t & 3) << 2;
    const int bn = t >> 2, bq = (t & 3) << 2;
    const float* Ap = A  + (size_t)(m0 + am) * lda + ak;
    const float* Bp = Bm + (size_t)(n0 + bn) * ldb + bq;
    float acc[4][4] = {};
    for (int kb = 0; kb < K; kb += 16) {
        float4 a = *(const float4*)(Ap + kb);
        float4 b = *(const float4*)(Bp + kb);
        As[ak+0][am] = a.x; As[ak+1][am] = a.y; As[ak+2][am] = a.z; As[ak+3][am] = a.w;
        Bsb[bq+0][bn] = b.x; Bsb[bq+1][bn] = b.y; Bsb[bq+2][bn] = b.z; Bsb[bq+3][bn] = b.w;
        __syncthreads();
        #pragma unroll
        for (int k = 0; k < 16; ++k) {
            float4 av = *(const float4*)&As[k][ty << 2];
            float4 bv = *(const float4*)&Bsb[k][tx << 2];
            acc[0][0] += av.x*bv.x; acc[0][1] += av.x*bv.y; acc[0][2] += av.x*bv.z; acc[0][3] += av.x*bv.w;
            acc[1][0] += av.y*bv.x; acc[1][1] += av.y*bv.y; acc[1][2] += av.y*bv.z; acc[1][3] += av.y*bv.w;
            acc[2][0] += av.z*bv.x; acc[2][1] += av.z*bv.y; acc[2][2] += av.z*bv.z; acc[2][3] += av.z*bv.w;
            acc[3][0] += av.w*bv.x; acc[3][1] += av.w*bv.y; acc[3][2] += av.w*bv.z; acc[3][3] += av.w*bv.w;
        }
        __syncthreads();
    }
    #pragma unroll
    for (int i = 0; i < 4; ++i) {
        float4 r;
        r.x = acc[i][0]*alpha; r.y = acc[i][1]*alpha; r.z = acc[i][2]*alpha; r.w = acc[i][3]*alpha;
        *(float4*)&C[(size_t)(m0 + (ty << 2) + i) * ldc + n0 + (tx << 2)] = r;
    }
}

__global__ void k_prep_part(const float* __restrict__ Wq, const float* __restrict__ Wkv,
                            const float* __restrict__ Wo)
{
    const int b = blockIdx.x;
    const int isN = b >> 7, idx = b & 127;
    const int h = idx >> 4, sub = (idx >> 2) & 3, ks = idx & 3;
    const int m0 = (sub >> 1) * 64, n0 = (sub & 1) * 64, k0 = ks * 64;
    float* C = g_pp + ((size_t)(isN * 4 + ks) * 8 + h) * (DIMM * DIMM);
    if (!isN)
        f32_nt_core(Wq + h * 256 + k0, Wkv + h * 256 + k0, C,
                    INNER, 2 * INNER, DIMM, 64, 1.0f, m0, n0);
    else
        f32_nn_core(Wkv + INNER + h * 256 + k0, Wo + ((size_t)h * 256 + k0) * DIMM, C,
                    2 * INNER, DIMM, DIMM, 64, 1.0f, m0, n0);
}

__global__ void k_prep_red()
{
    const int i = blockIdx.x * 256 + threadIdx.x;   // float4 idx, 65536 total
    const int isN = i >> 15, j = i & 32767;
    const int h = j >> 12, e = j & 4095;
    const float4* pp = (const float4*)g_pp;
    float4 r = make_float4(0.f, 0.f, 0.f, 0.f);
    #pragma unroll
    for (int ks = 0; ks < 4; ks++) {
        float4 a = pp[((size_t)(isN * 4 + ks) * 8 + h) * 4096 + e];
        r.x += a.x; r.y += a.y; r.z += a.z; r.w += a.w;
    }
    if (!isN) {
        r.x *= QSCALE; r.y *= QSCALE; r.z *= QSCALE; r.w *= QSCALE;
        ((float4*)g_m)[(size_t)h * 4096 + e] = r;
    } else {
        ((float4*)g_n)[(size_t)h * 4096 + e] = r;
    }
}

// ===========================================================================
// k_final_part (R10): per (h, bt) partial_h = PI_h @ N_h, combine fused into
// the A loader, 256 threads.
// ===========================================================================
__global__ void __launch_bounds__(256) k_final_part()
{
    __shared__ float As[32][72];
    __shared__ float Bsb[32][136];
    const int h = blockIdx.x, bt = blockIdx.y;
    const int z = bt * HEADS + h;
    const float* B = g_n + (size_t)h * DIMM * DIMM;
    float*       C = g_fp + (size_t)z * NL * DIMM;

    const int t    = threadIdx.x;
    const int warp = t >> 5, lane = t & 31;
    const int grp  = lane >> 2, qid = lane & 3;
    const int wm   = (warp & 3) * 16, wn = (warp >> 2) * 64;

    const int arow = t >> 2, ak0 = (t & 3) * 8;

    float2 ml0 = g_ml2[(size_t)(z*2  ) * NL + arow];
    float2 ml1 = g_ml2[(size_t)(z*2+1) * NL + arow];
    const float mm = fmaxf(ml0.x, ml1.x);
    const float a0 = __expf(ml0.x - mm), a1 = __expf(ml1.x - mm);
    const float il = 1.0f / (ml0.y * a0 + ml1.y * a1);
    const float e0 = a0 * il, e1 = a1 * il;

    const float* O0 = g_po + (size_t)(z*2  ) * NL * DIMM + (size_t)arow * DIMM + ak0;
    const float* O1 = g_po + (size_t)(z*2+1) * NL * DIMM + (size_t)arow * DIMM + ak0;
    const int brow = t >> 3, bcol = (t & 7) * 16;
    const float* Bp = B + (size_t)brow * DIMM + bcol;

    float acc[8][4];
    #pragma unroll
    for (int j = 0; j < 8; j++)
        #pragma unroll
        for (int i = 0; i < 4; i++) acc[j][i] = 0.f;

    float4 o0[2], o1[2], br[4];
    #pragma unroll
    for (int i = 0; i < 2; i++) {
        o0[i] = *(const float4*)(O0 + 4*i);
        o1[i] = *(const float4*)(O1 + 4*i);
    }
    #pragma unroll
    for (int i = 0; i < 4; i++) br[i] = *(const float4*)(Bp + 4*i);

    const int nk = DIMM / 32;   // 4
    for (int c = 0; c < nk; c++) {
        #pragma unroll
        for (int i = 0; i < 2; i++) {
            const int kc = ak0 + 4*i;
            As[kc+0][arow] = cf(e0*o0[i].x + e1*o1[i].x);
            As[kc+1][arow] = cf(e0*o0[i].y + e1*o1[i].y);
            As[kc+2][arow] = cf(e0*o0[i].z + e1*o1[i].z);
            As[kc+3][arow] = cf(e0*o0[i].w + e1*o1[i].w);
        }
        #pragma unroll
        for (int i = 0; i < 4; i++) {
            float4 v;
            v.x = cf(br[i].x); v.y = cf(br[i].y);
            v.z = cf(br[i].z); v.w = cf(br[i].w);
            *(float4*)&Bsb[brow][bcol + 4*i] = v;
        }
        __syncthreads();
        if (c + 1 < nk) {
            #pragma unroll
            for (int i = 0; i < 2; i++) {
                o0[i] = *(const float4*)(O0 + (c+1)*32 + 4*i);
                o1[i] = *(const float4*)(O1 + (c+1)*32 + 4*i);
            }
            const float* Bp2 = Bp + (size_t)(c + 1) * 32 * DIMM;
            #pragma unroll
            for (int i = 0; i < 4; i++) br[i] = *(const float4*)(Bp2 + 4*i);
        }
        #pragma unroll
        for (int kk = 0; kk < 32; kk += 8) {
            unsigned a[4], b[8][2];
            a[0] = __float_as_uint(As[kk+qid  ][wm+grp  ]);
            a[1] = __float_as_uint(As[kk+qid  ][wm+grp+8]);
            a[2] = __float_as_uint(As[kk+qid+4][wm+grp  ]);
            a[3] = __float_as_uint(As[kk+qid+4][wm+grp+8]);
            #pragma unroll
            for (int j = 0; j < 8; j++) {
                b[j][0] = __float_as_uint(Bsb[kk+qid  ][wn+8*j+grp]);
                b[j][1] = __float_as_uint(Bsb[kk+qid+4][wn+8*j+grp]);
            }
            #pragma unroll
            for (int j = 0; j < 8; j++) mma8(acc[j], a, b[j]);
        }
        __syncthreads();
    }
    #pragma unroll
    for (int j = 0; j < 8; j++) {
        const int col = wn + 8*j + 2*qid;
        *(float2*)&C[(size_t)(wm+grp  ) * DIMM + col] = make_float2(acc[j][0], acc[j][1]);
        *(float2*)&C[(size_t)(wm+grp+8) * DIMM + col] = make_float2(acc[j][2], acc[j][3]);
    }
}

// reduce 8 per-head partials -> out
__global__ void k_final_red(float* __restrict__ out)
{
    const int i = blockIdx.x * 256 + threadIdx.x;   // float4 index, 32768 total
    const int bt = i >> 11, inner = i & 2047;
    const float4* fp = (const float4*)g_fp;
    float4 r = make_float4(0.f, 0.f, 0.f, 0.f);
    #pragma unroll
    for (int h = 0; h < 8; h++) {
        float4 a = fp[((size_t)bt * 8 + h) * 2048 + inner];
        r.x += a.x; r.y += a.y; r.z += a.z; r.w += a.w;
    }
    ((float4*)out)[i] = r;
}

// ---------------------------------------------------------------------------

extern "C" void kernel_launch(void* const* d_in, const int* in_sizes, int n_in,
                              void* d_out, int out_size)
{
    const float* tensor  = (const float*)d_in[0];
    const float* latents = (const float*)d_in[1];
    const float* Wq      = (const float*)d_in[2];
    const float* Wkv     = (const float*)d_in[3];
    const float* Wo      = (const float*)d_in[4];
    float*       out     = (float*)d_out;

    (void)in_sizes; (void)n_in; (void)out_size;

    cudaFuncSetAttribute(k_flash, cudaFuncAttributeMaxDynamicSharedMemorySize, FLASH_SMEM);

    k_prep_part <<<256, 256>>>(Wq, Wkv, Wo);
    k_prep_red  <<<256, 256>>>();
    k_flash     <<<2 * BTT * HEADS, 256, FLASH_SMEM>>>(tensor, latents);
    k_final_part<<<dim3(HEADS, BTT), 256>>>();
    k_final_red <<<(BTT * NL * DIMM / 4) / 256, 256>>>(out);
}

// round 12
// speedup vs baseline: 1.1262x; 1.1262x over previous
#include <cuda_runtime.h>
#include <math.h>

// Problem constants
#define BTT     16
#define NM      1024
#define NL      64
#define NKV     1088
#define DIMM    128
#define HEADS   8
#define INNER   2048
#define QSCALE  0.08838834764831845f   // 128^-0.5
#define KVHALF  544

// Static device scratch
static __device__ float  g_pp[2 * 4 * 8 * DIMM * DIMM];       // split-K prep partials
static __device__ float  g_m [HEADS * DIMM * DIMM];           // M_h = scale*Wq_h@Wk_h^T
static __device__ float  g_n [HEADS * DIMM * DIMM];           // N_h = Wv_h@Wo_h
static __device__ float  g_po[2 * BTT * HEADS * NL * DIMM];   // un-normalized O halves
static __device__ float2 g_ml2[2 * BTT * HEADS * NL];         // (m, l) per half per row

// fp32 -> tf32 round-to-nearest
__device__ __forceinline__ float cf(float x){
    unsigned u; asm("cvt.rna.tf32.f32 %0, %1;" : "=r"(u) : "f"(x));
    return __uint_as_float(u);
}

__device__ __forceinline__ void mma8(float* d, const unsigned* a, const unsigned* b){
    asm volatile("mma.sync.aligned.m16n8k8.row.col.f32.tf32.tf32.f32 "
        "{%0,%1,%2,%3}, {%4,%5,%6,%7}, {%8,%9}, {%0,%1,%2,%3};"
        : "+f"(d[0]), "+f"(d[1]), "+f"(d[2]), "+f"(d[3])
        : "r"(a[0]), "r"(a[1]), "r"(a[2]), "r"(a[3]), "r"(b[0]), "r"(b[1]));
}

// row r of concat(tensor[bt], latents[bt])
__device__ __forceinline__ const float* row_ptr(
    const float* __restrict__ tensor, const float* __restrict__ latents, int bt, int r)
{
    return (r < NM) ? tensor  + ((size_t)bt * NM + r)        * DIMM
                    : latents + ((size_t)bt * NL + (r - NM)) * DIMM;
}

// ===========================================================================
// Flash building blocks (R10, proven): 256 threads (8 warps).
// A resident in smem At[k][72] (tf32). B double-buffered [2][32][136].
// ===========================================================================
#define BSW 4352   // words per Bs buffer (32*136)

// full-width fragment compute: warp tile 16x64 (acc[8][4])
__device__ __forceinline__ void frag_compute(
    const float* __restrict__ At, const float* __restrict__ Bs,
    float acc[8][4], int wm, int wn, int grp, int qid, int kbase)
{
    #pragma unroll
    for (int kk = 0; kk < 32; kk += 8) {
        unsigned a[4], b[8][2];
        const int k0 = kbase + kk;
        a[0] = __float_as_uint(At[(k0+qid  )*72 + wm+grp  ]);
        a[1] = __float_as_uint(At[(k0+qid  )*72 + wm+grp+8]);
        a[2] = __float_as_uint(At[(k0+qid+4)*72 + wm+grp  ]);
        a[3] = __float_as_uint(At[(k0+qid+4)*72 + wm+grp+8]);
        #pragma unroll
        for (int j = 0; j < 8; j++) {
            b[j][0] = __float_as_uint(Bs[(kk+qid  )*136 + wn+8*j+grp]);
            b[j][1] = __float_as_uint(Bs[(kk+qid+4)*136 + wn+8*j+grp]);
        }
        #pragma unroll
        for (int j = 0; j < 8; j++) mma8(acc[j], a, b[j]);
    }
}

// half-width fragment compute: warp tile 16x32 (acc[4][4]) — lower reg pressure
__device__ __forceinline__ void frag_compute_h(
    const float* __restrict__ At, const float* __restrict__ Bs,
    float acc[4][4], int wm, int wn2, int grp, int qid, int kbase)
{
    #pragma unroll
    for (int kk = 0; kk < 32; kk += 8) {
        unsigned a[4], b[4][2];
        const int k0 = kbase + kk;
        a[0] = __float_as_uint(At[(k0+qid  )*72 + wm+grp  ]);
        a[1] = __float_as_uint(At[(k0+qid  )*72 + wm+grp+8]);
        a[2] = __float_as_uint(At[(k0+qid+4)*72 + wm+grp  ]);
        a[3] = __float_as_uint(At[(k0+qid+4)*72 + wm+grp+8]);
        #pragma unroll
        for (int j = 0; j < 4; j++) {
            b[j][0] = __float_as_uint(Bs[(kk+qid  )*136 + wn2+8*j+grp]);
            b[j][1] = __float_as_uint(Bs[(kk+qid+4)*136 + wn2+8*j+grp]);
        }
        #pragma unroll
        for (int j = 0; j < 4; j++) mma8(acc[j], a, b[j]);
    }
}

__device__ __forceinline__ void stage_nn(float* Bs, const float4* pre, int br, int bc){
    #pragma unroll
    for (int i = 0; i < 4; i++) {
        float4 v;
        v.x = cf(pre[i].x); v.y = cf(pre[i].y);
        v.z = cf(pre[i].z); v.w = cf(pre[i].w);
        *(float4*)&Bs[br*136 + bc + 4*i] = v;
    }
}

__device__ __forceinline__ void stage_tb_h(float* Bs, const float4* pre, int bn, int bk0){
    #pragma unroll
    for (int i = 0; i < 2; i++) {
        const int k = bk0 + 4*i;
        Bs[(k+0)*136 + bn] = cf(pre[i].x);
        Bs[(k+1)*136 + bn] = cf(pre[i].y);
        Bs[(k+2)*136 + bn] = cf(pre[i].z);
        Bs[(k+3)*136 + bn] = cf(pre[i].w);
    }
}

// NN with contiguous weight B[k][n] (ldb row stride), K multiple of 32
__device__ __forceinline__ void gemm_w(
    const float* __restrict__ At, const float* __restrict__ Bg, int ldb, int K,
    float acc[8][4], float* __restrict__ BsBase,
    int wm, int wn, int grp, int qid, int t)
{
    const int br = t >> 3, bc = (t & 7) * 16;
    const float* Bp = Bg + (size_t)br * ldb + bc;
    float4 pre[4];
    #pragma unroll
    for (int i = 0; i < 4; i++) pre[i] = *(const float4*)(Bp + 4*i);
    stage_nn(BsBase, pre, br, bc);
    const int nk = K / 32;
    for (int c = 0; c < nk; c++) {
        __syncthreads();
        if (c + 1 < nk) {
            const float* Bp2 = Bp + (size_t)(c + 1) * 32 * ldb;
            #pragma unroll
            for (int i = 0; i < 4; i++) pre[i] = *(const float4*)(Bp2 + 4*i);
        }
        frag_compute(At, BsBase + (c & 1) * BSW, acc, wm, wn, grp, qid, c * 32);
        if (c + 1 < nk) stage_nn(BsBase + ((c + 1) & 1) * BSW, pre, br, bc);
    }
}

// TRANSB over in-rows, half width (64 kv rows): B row = concat row (row0+bn)
__device__ __forceinline__ void gemm_tb_h(
    const float* __restrict__ At,
    const float* __restrict__ tensor, const float* __restrict__ latents,
    int bt, int row0, int validN, float acc[4][4], float* __restrict__ BsBase,
    int wm, int wn2, int grp, int qid, int t)
{
    const int bn = t >> 2, bk0 = (t & 3) * 8;
    const bool v = bn < validN;
    const float* Bp = row_ptr(tensor, latents, bt, row0 + (v ? bn : 0)) + bk0;
    float4 pre[2];
    #pragma unroll
    for (int i = 0; i < 2; i++)
        pre[i] = v ? *(const float4*)(Bp + 4*i) : make_float4(0.f,0.f,0.f,0.f);
    stage_tb_h(BsBase, pre, bn, bk0);
    for (int c = 0; c < DIMM; c += 32) {
        __syncthreads();
        if (c + 32 < DIMM) {
            #pragma unroll
            for (int i = 0; i < 2; i++)
                pre[i] = v ? *(const float4*)(Bp + (c + 32) + 4*i)
                           : make_float4(0.f,0.f,0.f,0.f);
        }
        frag_compute_h(At, BsBase + ((c >> 5) & 1) * BSW, acc, wm, wn2, grp, qid, c);
        if (c + 32 < DIMM) stage_tb_h(BsBase + (((c >> 5) + 1) & 1) * BSW, pre, bn, bk0);
    }
}

// NN over in-rows: B row = concat row (row0 + c + br), K = kv count (mult of 32)
__device__ __forceinline__ void gemm_nn_in(
    const float* __restrict__ At,
    const float* __restrict__ tensor, const float* __restrict__ latents,
    int bt, int row0, int K, float acc[8][4], float* __restrict__ BsBase,
    int wm, int wn, int grp, int qid, int t)
{
    const int br = t >> 3, bc = (t & 7) * 16;
    float4 pre[4];
    {
        const float* Bp = row_ptr(tensor, latents, bt, row0 + br) + bc;
        #pragma unroll
        for (int i = 0; i < 4; i++) pre[i] = *(const float4*)(Bp + 4*i);
    }
    stage_nn(BsBase, pre, br, bc);
    for (int c = 0; c < K; c += 32) {
        __syncthreads();
        if (c + 32 < K) {
            const float* Bp2 = row_ptr(tensor, latents, bt, row0 + c + 32 + br) + bc;
            #pragma unroll
            for (int i = 0; i < 4; i++) pre[i] = *(const float4*)(Bp2 + 4*i);
        }
        frag_compute(At, BsBase + ((c >> 5) & 1) * BSW, acc, wm, wn, grp, qid, c);
        if (c + 32 < K) stage_nn(BsBase + (((c >> 5) + 1) & 1) * BSW, pre, br, bc);
    }
}

// ===========================================================================
// k_flash (R10, proven): grid 256 = (bt,h,half), tf32, double-buffered B.
// ===========================================================================
#define FLASH_WORDS (9216 + 9216 + 2*BSW + 192)
#define FLASH_SMEM  (FLASH_WORDS * 4)

__global__ void __launch_bounds__(256, 2) k_flash(
    const float* __restrict__ tensor, const float* __restrict__ latents)
{
    extern __shared__ float sm[];
    float* QWt   = sm;                    // [128][72]
    float* SXt   = sm + 9216;             // staging / S / P [128][72]
    float* Bs    = sm + 2*9216;           // [2][32][136]
    float* m_run = Bs + 2*BSW;            // [64]
    float* l_run = m_run + 64;
    float* rsc   = l_run + 64;

    const int zz = blockIdx.x;
    const int z = zz >> 1, half = zz & 1;
    const int bt = z >> 3, h = z & 7;
    const int kvbase = half * KVHALF;

    const int t = threadIdx.x, warp = t >> 5, lane = t & 31;
    const int grp = lane >> 2, qid = lane & 3;
    const int wm = (warp & 3) * 16;
    const int wn = (warp >> 2) * 64;      // full-width N offset
    const int wn2 = (warp >> 2) * 32;     // half-width N offset

    if (t < 64) { m_run[t] = -INFINITY; l_run[t] = 0.f; }

    // stage latents[bt] (64x128) transposed -> SXt[k][r]
    {
        const int r = t >> 2, k0 = (t & 3) * 32;
        const float* Lp = latents + (size_t)bt * NL * DIMM + (size_t)r * DIMM + k0;
        #pragma unroll
        for (int i = 0; i < 8; i++) {
            float4 v = *(const float4*)(Lp + 4*i);
            const int k = k0 + 4*i;
            SXt[(k+0)*72 + r] = cf(v.x);
            SXt[(k+1)*72 + r] = cf(v.y);
            SXt[(k+2)*72 + r] = cf(v.z);
            SXt[(k+3)*72 + r] = cf(v.w);
        }
    }
    __syncthreads();

    // QW = lat @ M_h
    {
        float qacc[8][4];
        #pragma unroll
        for (int j = 0; j < 8; j++)
            #pragma unroll
            for (int i = 0; i < 4; i++) qacc[j][i] = 0.f;
        gemm_w(SXt, g_m + (size_t)h * DIMM * DIMM, DIMM, DIMM,
               qacc, Bs, wm, wn, grp, qid, t);
        #pragma unroll
        for (int j = 0; j < 8; j++) {
            const int c = wn + 8*j + 2*qid;
            QWt[(c  )*72 + wm+grp  ] = cf(qacc[j][0]);
            QWt[(c+1)*72 + wm+grp  ] = cf(qacc[j][1]);
            QWt[(c  )*72 + wm+grp+8] = cf(qacc[j][2]);
            QWt[(c+1)*72 + wm+grp+8] = cf(qacc[j][3]);
        }
    }
    // no sync needed: first S-chunk's top barrier orders QWt stores before reads

    float O[8][4];
    #pragma unroll
    for (int j = 0; j < 8; j++)
        #pragma unroll
        for (int i = 0; i < 4; i++) O[j][i] = 0.f;

    for (int kv0 = 0; kv0 < KVHALF; kv0 += 128) {
        const int valid = (KVHALF - kv0 < 128) ? (KVHALF - kv0) : 128;  // 128 or 32

        // S block = QW @ in_blk^T in two N=64 halves (16-reg sacc, no spills)
        #pragma unroll
        for (int hn = 0; hn < 2; hn++) {
            const int validh = valid - hn * 64;
            if (validh > 0) {
                const int vh = validh < 64 ? validh : 64;
                float sacc[4][4];
                #pragma unroll
                for (int j = 0; j < 4; j++)
                    #pragma unroll
                    for (int i = 0; i < 4; i++) sacc[j][i] = 0.f;
                gemm_tb_h(QWt, tensor, latents, bt, kvbase + kv0 + hn * 64, vh,
                          sacc, Bs, wm, wn2, grp, qid, t);
                #pragma unroll
                for (int j = 0; j < 4; j++) {
                    const int c = hn * 64 + wn2 + 8*j + 2*qid;
                    if (c < valid) {
                        SXt[(c  )*72 + wm+grp  ] = sacc[j][0];
                        SXt[(c  )*72 + wm+grp+8] = sacc[j][2];
                    }
                    if (c + 1 < valid) {
                        SXt[(c+1)*72 + wm+grp  ] = sacc[j][1];
                        SXt[(c+1)*72 + wm+grp+8] = sacc[j][3];
                    }
                }
            }
        }
        __syncthreads();

        // online softmax: 4 threads per row, interleaved columns (bank-clean)
        {
            const int row = t >> 2, part = t & 3;
            const float mo = m_run[row];
            float mx = mo;
            #pragma unroll 8
            for (int i = 0; i < 32; i++) {
                const int c = part + 4*i;
                if (c < valid) mx = fmaxf(mx, SXt[c*72 + row]);
            }
            mx = fmaxf(mx, __shfl_xor_sync(0xffffffffu, mx, 1));
            mx = fmaxf(mx, __shfl_xor_sync(0xffffffffu, mx, 2));
            float s = 0.f;
            #pragma unroll 8
            for (int i = 0; i < 32; i++) {
                const int c = part + 4*i;
                if (c < valid) {
                    const float e = __expf(SXt[c*72 + row] - mx);
                    SXt[c*72 + row] = cf(e);
                    s += e;
                }
            }
            s += __shfl_xor_sync(0xffffffffu, s, 1);
            s += __shfl_xor_sync(0xffffffffu, s, 2);
            if (part == 0) {
                const float scale = __expf(mo - mx);
                l_run[row] = l_run[row] * scale + s;
                m_run[row] = mx;
                rsc[row]   = scale;
            }
        }
        __syncthreads();

        // rescale O, then O += P @ in_blk
        {
            const float s0 = rsc[wm+grp], s1 = rsc[wm+grp+8];
            #pragma unroll
            for (int j = 0; j < 8; j++) {
                O[j][0] *= s0; O[j][1] *= s0;
                O[j][2] *= s1; O[j][3] *= s1;
            }
        }
        gemm_nn_in(SXt, tensor, latents, bt, kvbase + kv0, valid,
                   O, Bs, wm, wn, grp, qid, t);
        __syncthreads();
    }

    if (t < 64) g_ml2[(size_t)zz * NL + t] = make_float2(m_run[t], l_run[t]);
    float* P = g_po + (size_t)zz * NL * DIMM;
    #pragma unroll
    for (int j = 0; j < 8; j++) {
        const int c = wn + 8*j + 2*qid;
        *(float2*)&P[(size_t)(wm+grp  ) * DIMM + c] = make_float2(O[j][0], O[j][1]);
        *(float2*)&P[(size_t)(wm+grp+8) * DIMM + c] = make_float2(O[j][2], O[j][3]);
    }
}

// ===========================================================================
// fp32 64x64 cores for split-K weight precompute (proven)
// ===========================================================================
__device__ __forceinline__ void f32_nn_core(
    const float* __restrict__ A, const float* __restrict__ B, float* __restrict__ C,
    int lda, int ldb, int ldc, int K, float alpha, int m0, int n0)
{
    __shared__ float As[16][68];
    __shared__ float Bsb[16][68];
    const int t  = threadIdx.x;
    const int tx = t & 15, ty = t >> 4;
    const int am = t >> 2, ak = (t & 3) << 2;
    const int bk = t >> 4, bn = (t & 15) << 2;
    const float* Ap = A + (size_t)(m0 + am) * lda + ak;
    const float* Bp = B + (size_t)bk * ldb + n0 + bn;
    float acc[4][4] = {};
    for (int kb = 0; kb < K; kb += 16) {
        float4 a = *(const float4*)(Ap + kb);
        float4 b = *(const float4*)(Bp + (size_t)kb * ldb);
        As[ak+0][am] = a.x; As[ak+1][am] = a.y; As[ak+2][am] = a.z; As[ak+3][am] = a.w;
        *(float4*)&Bsb[bk][bn] = b;
        __syncthreads();
        #pragma unroll
        for (int k = 0; k < 16; ++k) {
            float4 av = *(const float4*)&As[k][ty << 2];
            float4 bv = *(const float4*)&Bsb[k][tx << 2];
            acc[0][0] += av.x*bv.x; acc[0][1] += av.x*bv.y; acc[0][2] += av.x*bv.z; acc[0][3] += av.x*bv.w;
            acc[1][0] += av.y*bv.x; acc[1][1] += av.y*bv.y; acc[1][2] += av.y*bv.z; acc[1][3] += av.y*bv.w;
            acc[2][0] += av.z*bv.x; acc[2][1] += av.z*bv.y; acc[2][2] += av.z*bv.z; acc[2][3] += av.z*bv.w;
            acc[3][0] += av.w*bv.x; acc[3][1] += av.w*bv.y; acc[3][2] += av.w*bv.z; acc[3][3] += av.w*bv.w;
        }
        __syncthreads();
    }
    #pragma unroll
    for (int i = 0; i < 4; ++i) {
        float4 r;
        r.x = acc[i][0]*alpha; r.y = acc[i][1]*alpha; r.z = acc[i][2]*alpha; r.w = acc[i][3]*alpha;
        *(float4*)&C[(size_t)(m0 + (ty << 2) + i) * ldc + n0 + (tx << 2)] = r;
    }
}

__device__ __forceinline__ void f32_nt_core(
    const float* __restrict__ A, const float* __restrict__ Bm, float* __restrict__ C,
    int lda, int ldb, int ldc, int K, float alpha, int m0, int n0)
{
    __shared__ float As[16][68];
    __shared__ float Bsb[16][68];
    const int t  = threadIdx.x;
    const int tx = t & 15, ty = t >> 4;
    const int am = t >> 2, ak = (t & 3) << 2;
    const int bn = t >> 2, bq = (t & 3) << 2;
    const float* Ap = A  + (size_t)(m0 + am) * lda + ak;
    const float* Bp = Bm + (size_t)(n0 + bn) * ldb + bq;
    float acc[4][4] = {};
    for (int kb = 0; kb < K; kb += 16) {
        float4 a = *(const float4*)(Ap + kb);
        float4 b = *(const float4*)(Bp + kb);
        As[ak+0][am] = a.x; As[ak+1][am] = a.y; As[ak+2][am] = a.z; As[ak+3][am] = a.w;
        Bsb[bq+0][bn] = b.x; Bsb[bq+1][bn] = b.y; Bsb[bq+2][bn] = b.z; Bsb[bq+3][bn] = b.w;
        __syncthreads();
        #pragma unroll
        for (int k = 0; k < 16; ++k) {
            float4 av = *(const float4*)&As[k][ty << 2];
            float4 bv = *(const float4*)&Bsb[k][tx << 2];
            acc[0][0] += av.x*bv.x; acc[0][1] += av.x*bv.y; acc[0][2] += av.x*bv.z; acc[0][3] += av.x*bv.w;
            acc[1][0] += av.y*bv.x; acc[1][1] += av.y*bv.y; acc[1][2] += av.y*bv.z; acc[1][3] += av.y*bv.w;
            acc[2][0] += av.z*bv.x; acc[2][1] += av.z*bv.y; acc[2][2] += av.z*bv.z; acc[2][3] += av.z*bv.w;
            acc[3][0] += av.w*bv.x; acc[3][1] += av.w*bv.y; acc[3][2] += av.w*bv.z; acc[3][3] += av.w*bv.w;
        }
        __syncthreads();
    }
    #pragma unroll
    for (int i = 0; i < 4; ++i) {
        float4 r;
        r.x = acc[i][0]*alpha; r.y = acc[i][1]*alpha; r.z = acc[i][2]*alpha; r.w = acc[i][3]*alpha;
        *(float4*)&C[(size_t)(m0 + (ty << 2) + i) * ldc + n0 + (tx << 2)] = r;
    }
}

// k_prep_part: blocks 0..255 = split-K weight partials; 256..287 zero `out`
__global__ void k_prep_part(const float* __restrict__ Wq, const float* __restrict__ Wkv,
                            const float* __restrict__ Wo, float* __restrict__ out)
{
    const int b = blockIdx.x;
    if (b >= 256) {
        // zero the output buffer (atomic accumulation target for k_final_part)
        const int i = (b - 256) * 256 + threadIdx.x;   // 8192 threads
        float4* o4 = (float4*)out;
        #pragma unroll
        for (int j = 0; j < 4; j++)
            o4[i * 4 + j] = make_float4(0.f, 0.f, 0.f, 0.f);
        return;
    }
    const int isN = b >> 7, idx = b & 127;
    const int h = idx >> 4, sub = (idx >> 2) & 3, ks = idx & 3;
    const int m0 = (sub >> 1) * 64, n0 = (sub & 1) * 64, k0 = ks * 64;
    float* C = g_pp + ((size_t)(isN * 4 + ks) * 8 + h) * (DIMM * DIMM);
    if (!isN)
        f32_nt_core(Wq + h * 256 + k0, Wkv + h * 256 + k0, C,
                    INNER, 2 * INNER, DIMM, 64, 1.0f, m0, n0);
    else
        f32_nn_core(Wkv + INNER + h * 256 + k0, Wo + ((size_t)h * 256 + k0) * DIMM, C,
                    2 * INNER, DIMM, DIMM, 64, 1.0f, m0, n0);
}

__global__ void k_prep_red()
{
    const int i = blockIdx.x * 256 + threadIdx.x;   // float4 idx, 65536 total
    const int isN = i >> 15, j = i & 32767;
    const int h = j >> 12, e = j & 4095;
    const float4* pp = (const float4*)g_pp;
    float4 r = make_float4(0.f, 0.f, 0.f, 0.f);
    #pragma unroll
    for (int ks = 0; ks < 4; ks++) {
        float4 a = pp[((size_t)(isN * 4 + ks) * 8 + h) * 4096 + e];
        r.x += a.x; r.y += a.y; r.z += a.z; r.w += a.w;
    }
    if (!isN) {
        r.x *= QSCALE; r.y *= QSCALE; r.z *= QSCALE; r.w *= QSCALE;
        ((float4*)g_m)[(size_t)h * 4096 + e] = r;
    } else {
        ((float4*)g_n)[(size_t)h * 4096 + e] = r;
    }
}

// ===========================================================================
// k_final_part: per (h, bt) partial_h = PI_h @ N_h, combine fused into the
// A loader, 256 threads; accumulates DIRECTLY into out via atomicAdd (REDG).
// ===========================================================================
__global__ void __launch_bounds__(256) k_final_part(float* __restrict__ out)
{
    __shared__ float As[32][72];
    __shared__ float Bsb[32][136];
    const int h = blockIdx.x, bt = blockIdx.y;
    const int z = bt * HEADS + h;
    const float* B = g_n + (size_t)h * DIMM * DIMM;
    float*       C = out + (size_t)bt * NL * DIMM;

    const int t    = threadIdx.x;
    const int warp = t >> 5, lane = t & 31;
    const int grp  = lane >> 2, qid = lane & 3;
    const int wm   = (warp & 3) * 16, wn = (warp >> 2) * 64;

    const int arow = t >> 2, ak0 = (t & 3) * 8;

    float2 ml0 = g_ml2[(size_t)(z*2  ) * NL + arow];
    float2 ml1 = g_ml2[(size_t)(z*2+1) * NL + arow];
    const float mm = fmaxf(ml0.x, ml1.x);
    const float a0 = __expf(ml0.x - mm), a1 = __expf(ml1.x - mm);
    const float il = 1.0f / (ml0.y * a0 + ml1.y * a1);
    const float e0 = a0 * il, e1 = a1 * il;

    const float* O0 = g_po + (size_t)(z*2  ) * NL * DIMM + (size_t)arow * DIMM + ak0;
    const float* O1 = g_po + (size_t)(z*2+1) * NL * DIMM + (size_t)arow * DIMM + ak0;
    const int brow = t >> 3, bcol = (t & 7) * 16;
    const float* Bp = B + (size_t)brow * DIMM + bcol;

    float acc[8][4];
    #pragma unroll
    for (int j = 0; j < 8; j++)
        #pragma unroll
        for (int i = 0; i < 4; i++) acc[j][i] = 0.f;

    float4 o0[2], o1[2], br[4];
    #pragma unroll
    for (int i = 0; i < 2; i++) {
        o0[i] = *(const float4*)(O0 + 4*i);
        o1[i] = *(const float4*)(O1 + 4*i);
    }
    #pragma unroll
    for (int i = 0; i < 4; i++) br[i] = *(const float4*)(Bp + 4*i);

    const int nk = DIMM / 32;   // 4
    for (int c = 0; c < nk; c++) {
        #pragma unroll
        for (int i = 0; i < 2; i++) {
            const int kc = ak0 + 4*i;
            As[kc+0][arow] = cf(e0*o0[i].x + e1*o1[i].x);
            As[kc+1][arow] = cf(e0*o0[i].y + e1*o1[i].y);
            As[kc+2][arow] = cf(e0*o0[i].z + e1*o1[i].z);
            As[kc+3][arow] = cf(e0*o0[i].w + e1*o1[i].w);
        }
        #pragma unroll
        for (int i = 0; i < 4; i++) {
            float4 v;
            v.x = cf(br[i].x); v.y = cf(br[i].y);
            v.z = cf(br[i].z); v.w = cf(br[i].w);
            *(float4*)&Bsb[brow][bcol + 4*i] = v;
        }
        __syncthreads();
        if (c + 1 < nk) {
            #pragma unroll
            for (int i = 0; i < 2; i++) {
                o0[i] = *(const float4*)(O0 + (c+1)*32 + 4*i);
                o1[i] = *(const float4*)(O1 + (c+1)*32 + 4*i);
            }
            const float* Bp2 = Bp + (size_t)(c + 1) * 32 * DIMM;
            #pragma unroll
            for (int i = 0; i < 4; i++) br[i] = *(const float4*)(Bp2 + 4*i);
        }
        #pragma unroll
        for (int kk = 0; kk < 32; kk += 8) {
            unsigned a[4], b[8][2];
            a[0] = __float_as_uint(As[kk+qid  ][wm+grp  ]);
            a[1] = __float_as_uint(As[kk+qid  ][wm+grp+8]);
            a[2] = __float_as_uint(As[kk+qid+4][wm+grp  ]);
            a[3] = __float_as_uint(As[kk+qid+4][wm+grp+8]);
            #pragma unroll
            for (int j = 0; j < 8; j++) {
                b[j][0] = __float_as_uint(Bsb[kk+qid  ][wn+8*j+grp]);
                b[j][1] = __float_as_uint(Bsb[kk+qid+4][wn+8*j+grp]);
            }
            #pragma unroll
            for (int j = 0; j < 8; j++) mma8(acc[j], a, b[j]);
        }
        __syncthreads();
    }
    // accumulate into out (8 heads sum per element); out pre-zeroed in k_prep_part
    #pragma unroll
    for (int j = 0; j < 8; j++) {
        const int col = wn + 8*j + 2*qid;
        atomicAdd(&C[(size_t)(wm+grp  ) * DIMM + col    ], acc[j][0]);
        atomicAdd(&C[(size_t)(wm+grp  ) * DIMM + col + 1], acc[j][1]);
        atomicAdd(&C[(size_t)(wm+grp+8) * DIMM + col    ], acc[j][2]);
        atomicAdd(&C[(size_t)(wm+grp+8) * DIMM + col + 1], acc[j][3]);
    }
}

// ---------------------------------------------------------------------------

extern "C" void kernel_launch(void* const* d_in, const int* in_sizes, int n_in,
                              void* d_out, int out_size)
{
    const float* tensor  = (const float*)d_in[0];
    const float* latents = (const float*)d_in[1];
    const float* Wq      = (const float*)d_in[2];
    const float* Wkv     = (const float*)d_in[3];
    const float* Wo      = (const float*)d_in[4];
    float*       out     = (float*)d_out;

    (void)in_sizes; (void)n_in; (void)out_size;

    cudaFuncSetAttribute(k_flash, cudaFuncAttributeMaxDynamicSharedMemorySize, FLASH_SMEM);

    k_prep_part <<<288, 256>>>(Wq, Wkv, Wo, out);
    k_prep_red  <<<256, 256>>>();
    k_flash     <<<2 * BTT * HEADS, 256, FLASH_SMEM>>>(tensor, latents);
    k_final_part<<<dim3(HEADS, BTT), 256>>>(out);
}

// round 13
// speedup vs baseline: 1.3175x; 1.1699x over previous
#include <cuda_runtime.h>
#include <math.h>

// Problem constants
#define BTT     16
#define NM      1024
#define NL      64
#define NKV     1088
#define DIMM    128
#define HEADS   8
#define INNER   2048
#define QSCALE  0.08838834764831845f   // 128^-0.5
#define KVHALF  544

// Static device scratch
static __device__ float  g_pp[2 * 4 * 8 * DIMM * DIMM];       // split-K prep partials
static __device__ float  g_m [HEADS * DIMM * DIMM];           // M_h = scale*Wq_h@Wk_h^T
static __device__ float  g_n [HEADS * DIMM * DIMM];           // N_h = Wv_h@Wo_h
static __device__ float  g_po[2 * BTT * HEADS * NL * DIMM];   // un-normalized O halves
static __device__ float2 g_ml2[2 * BTT * HEADS * NL];         // (m, l) per half per row

// fp32 -> tf32 round-to-nearest
__device__ __forceinline__ float cf(float x){
    unsigned u; asm("cvt.rna.tf32.f32 %0, %1;" : "=r"(u) : "f"(x));
    return __uint_as_float(u);
}
__device__ __forceinline__ unsigned uu(float x){ return __float_as_uint(x); }

__device__ __forceinline__ void mma8(float* d, const unsigned* a, const unsigned* b){
    asm volatile("mma.sync.aligned.m16n8k8.row.col.f32.tf32.tf32.f32 "
        "{%0,%1,%2,%3}, {%4,%5,%6,%7}, {%8,%9}, {%0,%1,%2,%3};"
        : "+f"(d[0]), "+f"(d[1]), "+f"(d[2]), "+f"(d[3])
        : "r"(a[0]), "r"(a[1]), "r"(a[2]), "r"(a[3]), "r"(b[0]), "r"(b[1]));
}

// row r of concat(tensor[bt], latents[bt])
__device__ __forceinline__ const float* row_ptr(
    const float* __restrict__ tensor, const float* __restrict__ latents, int bt, int r)
{
    return (r < NM) ? tensor  + ((size_t)bt * NM + r)        * DIMM
                    : latents + ((size_t)bt * NL + (r - NM)) * DIMM;
}

#define BSW 4352   // words per B staging buffer (32*136)

// full-width fragment step: warp tile 16x64, A at At[(akbase+k)*72+..],
// B local chunk Bs[k*136+..], K=32
__device__ __forceinline__ void frag_full(
    const float* __restrict__ At, const float* __restrict__ Bs,
    float acc[8][4], int wm, int wn, int grp, int qid, int akbase)
{
    #pragma unroll
    for (int kk = 0; kk < 32; kk += 8) {
        unsigned a[4], b[8][2];
        const int k0 = akbase + kk;
        a[0] = uu(At[(k0+qid  )*72 + wm+grp  ]);
        a[1] = uu(At[(k0+qid  )*72 + wm+grp+8]);
        a[2] = uu(At[(k0+qid+4)*72 + wm+grp  ]);
        a[3] = uu(At[(k0+qid+4)*72 + wm+grp+8]);
        #pragma unroll
        for (int j = 0; j < 8; j++) {
            b[j][0] = uu(Bs[(kk+qid  )*136 + wn+8*j+grp]);
            b[j][1] = uu(Bs[(kk+qid+4)*136 + wn+8*j+grp]);
        }
        #pragma unroll
        for (int j = 0; j < 8; j++) mma8(acc[j], a, b[j]);
    }
}

// half-width fragment step: warp tile 16x32 (S phase)
__device__ __forceinline__ void frag_half(
    const float* __restrict__ At, const float* __restrict__ Bs,
    float acc[4][4], int wm, int wn2, int grp, int qid, int akbase)
{
    #pragma unroll
    for (int kk = 0; kk < 32; kk += 8) {
        unsigned a[4], b[4][2];
        const int k0 = akbase + kk;
        a[0] = uu(At[(k0+qid  )*72 + wm+grp  ]);
        a[1] = uu(At[(k0+qid  )*72 + wm+grp+8]);
        a[2] = uu(At[(k0+qid+4)*72 + wm+grp  ]);
        a[3] = uu(At[(k0+qid+4)*72 + wm+grp+8]);
        #pragma unroll
        for (int j = 0; j < 4; j++) {
            b[j][0] = uu(Bs[(kk+qid  )*136 + wn2+8*j+grp]);
            b[j][1] = uu(Bs[(kk+qid+4)*136 + wn2+8*j+grp]);
        }
        #pragma unroll
        for (int j = 0; j < 4; j++) mma8(acc[j], a, b[j]);
    }
}

// ===========================================================================
// k_flash: grid 128 = (bt, head-pair, kv-half), 512 threads (16 warps).
// Warps 0-7 = head A, 8-15 = head B; KV tiles staged ONCE per pair.
// smem words: QWt[2]x9216 | SXt[2]x9216 | Bs 4xBSW | stats 384 = 54656
// ===========================================================================
#define FLASH_WORDS (2*9216 + 2*9216 + 4*BSW + 384)
#define FLASH_SMEM  (FLASH_WORDS * 4)   // 218624 bytes

__global__ void __launch_bounds__(512, 1) k_flash(
    const float* __restrict__ tensor, const float* __restrict__ latents)
{
    extern __shared__ float sm[];
    const int zz = blockIdx.x;                 // 0..127
    const int half = zz & 1, hp = (zz >> 1) & 3, bt = zz >> 3;
    const int kvbase = half * KVHALF;

    const int t = threadIdx.x, warp = t >> 5, lane = t & 31;
    const int head = warp >> 3, w8 = warp & 7;
    const int grp = lane >> 2, qid = lane & 3;
    const int wm  = (w8 & 3) * 16;
    const int wn  = (w8 >> 2) * 64;
    const int wn2 = (w8 >> 2) * 32;
    const int hglob = hp * 2 + head;

    float* QWt   = sm + head * 9216;           // [128 dims][72]
    float* LATt  = sm + 18432;                 // latents transposed (shared; = SXt of head0)
    float* SXt   = sm + 18432 + head * 9216;   // scores/P [kv][72] per head
    float* BsAll = sm + 36864;                 // 4 x [32][136]
    float* stats = sm + 36864 + 4*BSW;         // m[128] | l[128] | rsc[128]
    float* m_run = stats + head * 64;
    float* l_run = stats + 128 + head * 64;
    float* rsc   = stats + 256 + head * 64;

    if (t < 128) { stats[t] = -INFINITY; stats[128 + t] = 0.f; }

    // stage latents[bt] (64x128) transposed -> LATt (shared by both heads)
    {
        const int r = t >> 3, k0 = (t & 7) * 16;
        const float* Lp = latents + (size_t)bt * NL * DIMM + (size_t)r * DIMM + k0;
        #pragma unroll
        for (int i = 0; i < 4; i++) {
            float4 v = *(const float4*)(Lp + 4*i);
            const int k = k0 + 4*i;
            LATt[(k+0)*72 + r] = cf(v.x);
            LATt[(k+1)*72 + r] = cf(v.y);
            LATt[(k+2)*72 + r] = cf(v.z);
            LATt[(k+3)*72 + r] = cf(v.w);
        }
    }
    __syncthreads();

    // ---- QW = lat @ M_h, each head double-buffered in its own buffer pair ----
    {
        const int ts = t & 255, hsel = t >> 8;
        float* BufBase = BsAll + hsel * 2 * BSW;           // staging target
        const float* Bg = g_m + (size_t)(hp * 2 + hsel) * DIMM * DIMM;
        const int br = ts >> 3, bc = (ts & 7) * 16;
        const float* Bp = Bg + (size_t)br * DIMM + bc;
        float4 pre[4];
        #pragma unroll
        for (int i = 0; i < 4; i++) pre[i] = *(const float4*)(Bp + 4*i);
        #pragma unroll
        for (int i = 0; i < 4; i++) {
            float4 v;
            v.x = cf(pre[i].x); v.y = cf(pre[i].y);
            v.z = cf(pre[i].z); v.w = cf(pre[i].w);
            *(float4*)&BufBase[br*136 + bc + 4*i] = v;
        }
        float qacc[8][4];
        #pragma unroll
        for (int j = 0; j < 8; j++)
            #pragma unroll
            for (int i = 0; i < 4; i++) qacc[j][i] = 0.f;
        const float* myBuf = BsAll + head * 2 * BSW;       // compute source
        for (int c = 0; c < 4; c++) {
            __syncthreads();
            if (c + 1 < 4) {
                const float* Bp2 = Bp + (size_t)(c + 1) * 32 * DIMM;
                #pragma unroll
                for (int i = 0; i < 4; i++) pre[i] = *(const float4*)(Bp2 + 4*i);
            }
            frag_full(LATt, myBuf + (c & 1) * BSW, qacc, wm, wn, grp, qid, c * 32);
            if (c + 1 < 4) {
                float* dst = BufBase + ((c + 1) & 1) * BSW;
                #pragma unroll
                for (int i = 0; i < 4; i++) {
                    float4 v;
                    v.x = cf(pre[i].x); v.y = cf(pre[i].y);
                    v.z = cf(pre[i].z); v.w = cf(pre[i].w);
                    *(float4*)&dst[br*136 + bc + 4*i] = v;
                }
            }
        }
        #pragma unroll
        for (int j = 0; j < 8; j++) {
            const int c = wn + 8*j + 2*qid;
            QWt[(c  )*72 + wm+grp  ] = cf(qacc[j][0]);
            QWt[(c+1)*72 + wm+grp  ] = cf(qacc[j][1]);
            QWt[(c  )*72 + wm+grp+8] = cf(qacc[j][2]);
            QWt[(c+1)*72 + wm+grp+8] = cf(qacc[j][3]);
        }
    }
    // first S sync orders QWt stores before reads

    float O[8][4];
    #pragma unroll
    for (int j = 0; j < 8; j++)
        #pragma unroll
        for (int i = 0; i < 4; i++) O[j][i] = 0.f;

    // S-phase staging role: 64 kv rows x 32 dims per chunk, conflict-free banks
    const int sbn = t & 63, skd = (t >> 6) * 4;            // kv row, dim base (0..28)
    // PV staging role: 32 kv rows x 128 dims per chunk
    const int pbr = t >> 4, pbc = (t & 15) * 8;

    for (int kv0 = 0; kv0 < KVHALF; kv0 += 128) {
        const int valid = (KVHALF - kv0 < 128) ? (KVHALF - kv0) : 128;  // 128 or 32

        // ---- S = QW @ in^T in two kv halves of 64, shared B staging ----
        #pragma unroll
        for (int hn = 0; hn < 2; hn++) {
            const int validh = valid - hn * 64;
            if (validh > 0) {
                const int vh = validh < 64 ? validh : 64;
                const bool v = sbn < vh;
                const float* Bp = row_ptr(tensor, latents, bt,
                                          kvbase + kv0 + hn*64 + (v ? sbn : 0)) + skd;
                float4 pre = v ? *(const float4*)Bp : make_float4(0.f,0.f,0.f,0.f);
                // stage chunk 0 (dims 0..31) into buf0
                {
                    float* dst = BsAll;
                    dst[(skd+0)*136 + sbn] = cf(pre.x);
                    dst[(skd+1)*136 + sbn] = cf(pre.y);
                    dst[(skd+2)*136 + sbn] = cf(pre.z);
                    dst[(skd+3)*136 + sbn] = cf(pre.w);
                }
                float sacc[4][4];
                #pragma unroll
                for (int j = 0; j < 4; j++)
                    #pragma unroll
                    for (int i = 0; i < 4; i++) sacc[j][i] = 0.f;
                for (int c = 0; c < 4; c++) {
                    __syncthreads();
                    if (c + 1 < 4)
                        pre = v ? *(const float4*)(Bp + (c+1)*32)
                                : make_float4(0.f,0.f,0.f,0.f);
                    frag_half(QWt, BsAll + (c & 1) * BSW, sacc, wm, wn2, grp, qid, c * 32);
                    if (c + 1 < 4) {
                        float* dst = BsAll + ((c + 1) & 1) * BSW;
                        dst[(skd+0)*136 + sbn] = cf(pre.x);
                        dst[(skd+1)*136 + sbn] = cf(pre.y);
                        dst[(skd+2)*136 + sbn] = cf(pre.z);
                        dst[(skd+3)*136 + sbn] = cf(pre.w);
                    }
                }
                #pragma unroll
                for (int j = 0; j < 4; j++) {
                    const int c = hn * 64 + wn2 + 8*j + 2*qid;
                    if (c < valid) {
                        SXt[(c  )*72 + wm+grp  ] = sacc[j][0];
                        SXt[(c  )*72 + wm+grp+8] = sacc[j][2];
                    }
                    if (c + 1 < valid) {
                        SXt[(c+1)*72 + wm+grp  ] = sacc[j][1];
                        SXt[(c+1)*72 + wm+grp+8] = sacc[j][3];
                    }
                }
            }
        }
        __syncthreads();

        // ---- online softmax: 2 heads x 64 rows x 4 parts = 512 threads ----
        {
            const int hs = t >> 8, row = (t >> 2) & 63, part = t & 3;
            float* SX = sm + 18432 + hs * 9216;
            float* mr = stats + hs * 64;
            float* lr = stats + 128 + hs * 64;
            float* rs = stats + 256 + hs * 64;
            const float mo = mr[row];
            float mx = mo;
            #pragma unroll 8
            for (int i = 0; i < 32; i++) {
                const int c = part + 4*i;
                if (c < valid) mx = fmaxf(mx, SX[c*72 + row]);
            }
            mx = fmaxf(mx, __shfl_xor_sync(0xffffffffu, mx, 1));
            mx = fmaxf(mx, __shfl_xor_sync(0xffffffffu, mx, 2));
            float s = 0.f;
            #pragma unroll 8
            for (int i = 0; i < 32; i++) {
                const int c = part + 4*i;
                if (c < valid) {
                    const float e = __expf(SX[c*72 + row] - mx);
                    SX[c*72 + row] = cf(e);
                    s += e;
                }
            }
            s += __shfl_xor_sync(0xffffffffu, s, 1);
            s += __shfl_xor_sync(0xffffffffu, s, 2);
            if (part == 0) {
                const float scale = __expf(mo - mx);
                lr[row] = lr[row] * scale + s;
                mr[row] = mx;
                rs[row] = scale;
            }
        }
        __syncthreads();

        // ---- rescale O, then O += P @ in (shared B staging, 32-kv chunks) ----
        {
            const float s0 = rsc[wm+grp], s1 = rsc[wm+grp+8];
            #pragma unroll
            for (int j = 0; j < 8; j++) {
                O[j][0] *= s0; O[j][1] *= s0;
                O[j][2] *= s1; O[j][3] *= s1;
            }
        }
        {
            const int nch = valid >> 5;                    // 4 or 1
            const float* Bp = row_ptr(tensor, latents, bt, kvbase + kv0 + pbr) + pbc;
            float4 p0 = *(const float4*)(Bp);
            float4 p1 = *(const float4*)(Bp + 4);
            // stage chunk 0 into buf0 (natural [kv][dim])
            {
                float* dst = BsAll + pbr * 136 + pbc;
                float4 w;
                w.x = cf(p0.x); w.y = cf(p0.y); w.z = cf(p0.z); w.w = cf(p0.w);
                *(float4*)dst = w;
                w.x = cf(p1.x); w.y = cf(p1.y); w.z = cf(p1.z); w.w = cf(p1.w);
                *(float4*)(dst + 4) = w;
            }
            for (int c = 0; c < nch; c++) {
                __syncthreads();
                if (c + 1 < nch) {
                    const float* Bp2 = row_ptr(tensor, latents, bt,
                                               kvbase + kv0 + (c+1)*32 + pbr) + pbc;
                    p0 = *(const float4*)(Bp2);
                    p1 = *(const float4*)(Bp2 + 4);
                }
                frag_full(SXt, BsAll + (c & 1) * BSW, O, wm, wn, grp, qid, c * 32);
                if (c + 1 < nch) {
                    float* dst = BsAll + ((c + 1) & 1) * BSW + pbr * 136 + pbc;
                    float4 w;
                    w.x = cf(p0.x); w.y = cf(p0.y); w.z = cf(p0.z); w.w = cf(p0.w);
                    *(float4*)dst = w;
                    w.x = cf(p1.x); w.y = cf(p1.y); w.z = cf(p1.z); w.w = cf(p1.w);
                    *(float4*)(dst + 4) = w;
                }
            }
        }
        __syncthreads();
    }

    // ---- epilogue: store (m,l) and un-normalized O ----
    if (t < 128) {
        const int hs = t >> 6, r = t & 63;
        const int zo = (bt * 8 + hp * 2 + hs) * 2 + half;
        g_ml2[(size_t)zo * NL + r] = make_float2(stats[hs*64 + r], stats[128 + hs*64 + r]);
    }
    float* P = g_po + (size_t)((bt * 8 + hglob) * 2 + half) * NL * DIMM;
    #pragma unroll
    for (int j = 0; j < 8; j++) {
        const int c = wn + 8*j + 2*qid;
        *(float2*)&P[(size_t)(wm+grp  ) * DIMM + c] = make_float2(O[j][0], O[j][1]);
        *(float2*)&P[(size_t)(wm+grp+8) * DIMM + c] = make_float2(O[j][2], O[j][3]);
    }
}

// ===========================================================================
// fp32 64x64 cores for split-K weight precompute (proven)
// ===========================================================================
__device__ __forceinline__ void f32_nn_core(
    const float* __restrict__ A, const float* __restrict__ B, float* __restrict__ C,
    int lda, int ldb, int ldc, int K, float alpha, int m0, int n0)
{
    __shared__ float As[16][68];
    __shared__ float Bsb[16][68];
    const int t  = threadIdx.x;
    const int tx = t & 15, ty = t >> 4;
    const int am = t >> 2, ak = (t & 3) << 2;
    const int bk = t >> 4, bn = (t & 15) << 2;
    const float* Ap = A + (size_t)(m0 + am) * lda + ak;
    const float* Bp = B + (size_t)bk * ldb + n0 + bn;
    float acc[4][4] = {};
    for (int kb = 0; kb < K; kb += 16) {
        float4 a = *(const float4*)(Ap + kb);
        float4 b = *(const float4*)(Bp + (size_t)kb * ldb);
        As[ak+0][am] = a.x; As[ak+1][am] = a.y; As[ak+2][am] = a.z; As[ak+3][am] = a.w;
        *(float4*)&Bsb[bk][bn] = b;
        __syncthreads();
        #pragma unroll
        for (int k = 0; k < 16; ++k) {
            float4 av = *(const float4*)&As[k][ty << 2];
            float4 bv = *(const float4*)&Bsb[k][tx << 2];
            acc[0][0] += av.x*bv.x; acc[0][1] += av.x*bv.y; acc[0][2] += av.x*bv.z; acc[0][3] += av.x*bv.w;
            acc[1][0] += av.y*bv.x; acc[1][1] += av.y*bv.y; acc[1][2] += av.y*bv.z; acc[1][3] += av.y*bv.w;
            acc[2][0] += av.z*bv.x; acc[2][1] += av.z*bv.y; acc[2][2] += av.z*bv.z; acc[2][3] += av.z*bv.w;
            acc[3][0] += av.w*bv.x; acc[3][1] += av.w*bv.y; acc[3][2] += av.w*bv.z; acc[3][3] += av.w*bv.w;
        }
        __syncthreads();
    }
    #pragma unroll
    for (int i = 0; i < 4; ++i) {
        float4 r;
        r.x = acc[i][0]*alpha; r.y = acc[i][1]*alpha; r.z = acc[i][2]*alpha; r.w = acc[i][3]*alpha;
        *(float4*)&C[(size_t)(m0 + (ty << 2) + i) * ldc + n0 + (tx << 2)] = r;
    }
}

__device__ __forceinline__ void f32_nt_core(
    const float* __restrict__ A, const float* __restrict__ Bm, float* __restrict__ C,
    int lda, int ldb, int ldc, int K, float alpha, int m0, int n0)
{
    __shared__ float As[16][68];
    __shared__ float Bsb[16][68];
    const int t  = threadIdx.x;
    const int tx = t & 15, ty = t >> 4;
    const int am = t >> 2, ak = (t & 3) << 2;
    const int bn = t >> 2, bq = (t & 3) << 2;
    const float* Ap = A  + (size_t)(m0 + am) * lda + ak;
    const float* Bp = Bm + (size_t)(n0 + bn) * ldb + bq;
    float acc[4][4] = {};
    for (int kb = 0; kb < K; kb += 16) {
        float4 a = *(const float4*)(Ap + kb);
        float4 b = *(const float4*)(Bp + kb);
        As[ak+0][am] = a.x; As[ak+1][am] = a.y; As[ak+2][am] = a.z; As[ak+3][am] = a.w;
        Bsb[bq+0][bn] = b.x; Bsb[bq+1][bn] = b.y; Bsb[bq+2][bn] = b.z; Bsb[bq+3][bn] = b.w;
        __syncthreads();
        #pragma unroll
        for (int k = 0; k < 16; ++k) {
            float4 av = *(const float4*)&As[k][ty << 2];
            float4 bv = *(const float4*)&Bsb[k][tx << 2];
            acc[0][0] += av.x*bv.x; acc[0][1] += av.x*bv.y; acc[0][2] += av.x*bv.z; acc[0][3] += av.x*bv.w;
            acc[1][0] += av.y*bv.x; acc[1][1] += av.y*bv.y; acc[1][2] += av.y*bv.z; acc[1][3] += av.y*bv.w;
            acc[2][0] += av.z*bv.x; acc[2][1] += av.z*bv.y; acc[2][2] += av.z*bv.z; acc[2][3] += av.z*bv.w;
            acc[3][0] += av.w*bv.x; acc[3][1] += av.w*bv.y; acc[3][2] += av.w*bv.z; acc[3][3] += av.w*bv.w;
        }
        __syncthreads();
    }
    #pragma unroll
    for (int i = 0; i < 4; ++i) {
        float4 r;
        r.x = acc[i][0]*alpha; r.y = acc[i][1]*alpha; r.z = acc[i][2]*alpha; r.w = acc[i][3]*alpha;
        *(float4*)&C[(size_t)(m0 + (ty << 2) + i) * ldc + n0 + (tx << 2)] = r;
    }
}

// k_prep_part: blocks 0..255 = split-K weight partials; 256..287 zero `out`
__global__ void k_prep_part(const float* __restrict__ Wq, const float* __restrict__ Wkv,
                            const float* __restrict__ Wo, float* __restrict__ out)
{
    const int b = blockIdx.x;
    if (b >= 256) {
        const int i = (b - 256) * 256 + threadIdx.x;
        float4* o4 = (float4*)out;
        #pragma unroll
        for (int j = 0; j < 4; j++)
            o4[i * 4 + j] = make_float4(0.f, 0.f, 0.f, 0.f);
        return;
    }
    const int isN = b >> 7, idx = b & 127;
    const int h = idx >> 4, sub = (idx >> 2) & 3, ks = idx & 3;
    const int m0 = (sub >> 1) * 64, n0 = (sub & 1) * 64, k0 = ks * 64;
    float* C = g_pp + ((size_t)(isN * 4 + ks) * 8 + h) * (DIMM * DIMM);
    if (!isN)
        f32_nt_core(Wq + h * 256 + k0, Wkv + h * 256 + k0, C,
                    INNER, 2 * INNER, DIMM, 64, 1.0f, m0, n0);
    else
        f32_nn_core(Wkv + INNER + h * 256 + k0, Wo + ((size_t)h * 256 + k0) * DIMM, C,
                    2 * INNER, DIMM, DIMM, 64, 1.0f, m0, n0);
}

__global__ void k_prep_red()
{
    const int i = blockIdx.x * 256 + threadIdx.x;
    const int isN = i >> 15, j = i & 32767;
    const int h = j >> 12, e = j & 4095;
    const float4* pp = (const float4*)g_pp;
    float4 r = make_float4(0.f, 0.f, 0.f, 0.f);
    #pragma unroll
    for (int ks = 0; ks < 4; ks++) {
        float4 a = pp[((size_t)(isN * 4 + ks) * 8 + h) * 4096 + e];
        r.x += a.x; r.y += a.y; r.z += a.z; r.w += a.w;
    }
    if (!isN) {
        r.x *= QSCALE; r.y *= QSCALE; r.z *= QSCALE; r.w *= QSCALE;
        ((float4*)g_m)[(size_t)h * 4096 + e] = r;
    } else {
        ((float4*)g_n)[(size_t)h * 4096 + e] = r;
    }
}

// ===========================================================================
// k_final_part: per (h, bt) partial_h = PI_h @ N_h, combine fused into the
// A loader, 256 threads; accumulates directly into out via atomicAdd.
// ===========================================================================
__global__ void __launch_bounds__(256) k_final_part(float* __restrict__ out)
{
    __shared__ float As[32][72];
    __shared__ float Bsb[32][136];
    const int h = blockIdx.x, bt = blockIdx.y;
    const int z = bt * HEADS + h;
    const float* B = g_n + (size_t)h * DIMM * DIMM;
    float*       C = out + (size_t)bt * NL * DIMM;

    const int t    = threadIdx.x;
    const int warp = t >> 5, lane = t & 31;
    const int grp  = lane >> 2, qid = lane & 3;
    const int wm   = (warp & 3) * 16, wn = (warp >> 2) * 64;

    const int arow = t >> 2, ak0 = (t & 3) * 8;

    float2 ml0 = g_ml2[(size_t)(z*2  ) * NL + arow];
    float2 ml1 = g_ml2[(size_t)(z*2+1) * NL + arow];
    const float mm = fmaxf(ml0.x, ml1.x);
    const float a0 = __expf(ml0.x - mm), a1 = __expf(ml1.x - mm);
    const float il = 1.0f / (ml0.y * a0 + ml1.y * a1);
    const float e0 = a0 * il, e1 = a1 * il;

    const float* O0 = g_po + (size_t)(z*2  ) * NL * DIMM + (size_t)arow * DIMM + ak0;
    const float* O1 = g_po + (size_t)(z*2+1) * NL * DIMM + (size_t)arow * DIMM + ak0;
    const int brow = t >> 3, bcol = (t & 7) * 16;
    const float* Bp = B + (size_t)brow * DIMM + bcol;

    float acc[8][4];
    #pragma unroll
    for (int j = 0; j < 8; j++)
        #pragma unroll
        for (int i = 0; i < 4; i++) acc[j][i] = 0.f;

    float4 o0[2], o1[2], br[4];
    #pragma unroll
    for (int i = 0; i < 2; i++) {
        o0[i] = *(const float4*)(O0 + 4*i);
        o1[i] = *(const float4*)(O1 + 4*i);
    }
    #pragma unroll
    for (int i = 0; i < 4; i++) br[i] = *(const float4*)(Bp + 4*i);

    const int nk = DIMM / 32;   // 4
    for (int c = 0; c < nk; c++) {
        #pragma unroll
        for (int i = 0; i < 2; i++) {
            const int kc = ak0 + 4*i;
            As[kc+0][arow] = cf(e0*o0[i].x + e1*o1[i].x);
            As[kc+1][arow] = cf(e0*o0[i].y + e1*o1[i].y);
            As[kc+2][arow] = cf(e0*o0[i].z + e1*o1[i].z);
            As[kc+3][arow] = cf(e0*o0[i].w + e1*o1[i].w);
        }
        #pragma unroll
        for (int i = 0; i < 4; i++) {
            float4 v;
            v.x = cf(br[i].x); v.y = cf(br[i].y);
            v.z = cf(br[i].z); v.w = cf(br[i].w);
            *(float4*)&Bsb[brow][bcol + 4*i] = v;
        }
        __syncthreads();
        if (c + 1 < nk) {
            #pragma unroll
            for (int i = 0; i < 2; i++) {
                o0[i] = *(const float4*)(O0 + (c+1)*32 + 4*i);
                o1[i] = *(const float4*)(O1 + (c+1)*32 + 4*i);
            }
            const float* Bp2 = Bp + (size_t)(c + 1) * 32 * DIMM;
            #pragma unroll
            for (int i = 0; i < 4; i++) br[i] = *(const float4*)(Bp2 + 4*i);
        }
        #pragma unroll
        for (int kk = 0; kk < 32; kk += 8) {
            unsigned a[4], b[8][2];
            a[0] = uu(As[kk+qid  ][wm+grp  ]);
            a[1] = uu(As[kk+qid  ][wm+grp+8]);
            a[2] = uu(As[kk+qid+4][wm+grp  ]);
            a[3] = uu(As[kk+qid+4][wm+grp+8]);
            #pragma unroll
            for (int j = 0; j < 8; j++) {
                b[j][0] = uu(Bsb[kk+qid  ][wn+8*j+grp]);
                b[j][1] = uu(Bsb[kk+qid+4][wn+8*j+grp]);
            }
            #pragma unroll
            for (int j = 0; j < 8; j++) mma8(acc[j], a, b[j]);
        }
        __syncthreads();
    }
    #pragma unroll
    for (int j = 0; j < 8; j++) {
        const int col = wn + 8*j + 2*qid;
        atomicAdd(&C[(size_t)(wm+grp  ) * DIMM + col    ], acc[j][0]);
        atomicAdd(&C[(size_t)(wm+grp  ) * DIMM + col + 1], acc[j][1]);
        atomicAdd(&C[(size_t)(wm+grp+8) * DIMM + col    ], acc[j][2]);
        atomicAdd(&C[(size_t)(wm+grp+8) * DIMM + col + 1], acc[j][3]);
    }
}

// ---------------------------------------------------------------------------

extern "C" void kernel_launch(void* const* d_in, const int* in_sizes, int n_in,
                              void* d_out, int out_size)
{
    const float* tensor  = (const float*)d_in[0];
    const float* latents = (const float*)d_in[1];
    const float* Wq      = (const float*)d_in[2];
    const float* Wkv     = (const float*)d_in[3];
    const float* Wo      = (const float*)d_in[4];
    float*       out     = (float*)d_out;

    (void)in_sizes; (void)n_in; (void)out_size;

    cudaFuncSetAttribute(k_flash, cudaFuncAttributeMaxDynamicSharedMemorySize, FLASH_SMEM);

    k_prep_part <<<288, 256>>>(Wq, Wkv, Wo, out);
    k_prep_red  <<<256, 256>>>();
    k_flash     <<<BTT * HEADS, 512, FLASH_SMEM>>>(tensor, latents);
    k_final_part<<<dim3(HEADS, BTT), 256>>>(out);
}